// round 13
// baseline (speedup 1.0000x reference)
#include <cuda_runtime.h>
#include <cuda_fp16.h>
#include <cstdint>

constexpr int Bc = 4, Sc = 2048, Ec = 512, Hc = 8, DKc = 64;

__device__ __align__(256) __half g_Af [Bc * Hc * Sc * DKc];  // fp16 cos(x+theta), head-major
__device__ __align__(256) __half g_AOf[Bc * Sc * Ec];        // attention out, fp16
__device__ __align__(256) __half g_Wf [Ec * Ec];             // W fp16

// ---------------------------------------------------------------------------
// helpers
// ---------------------------------------------------------------------------
__device__ __forceinline__ uint32_t smem_u32(const void* p) {
    uint32_t a;
    asm("{ .reg .u64 t; cvta.to.shared.u64 t, %1; cvt.u32.u64 %0, t; }" : "=r"(a) : "l"(p));
    return a;
}
__device__ __forceinline__ void ldsm_x4(uint32_t* r, uint32_t addr) {
    asm volatile("ldmatrix.sync.aligned.m8n8.x4.shared.b16 {%0,%1,%2,%3}, [%4];"
                 : "=r"(r[0]), "=r"(r[1]), "=r"(r[2]), "=r"(r[3]) : "r"(addr));
}
__device__ __forceinline__ void ldsm_x4_t(uint32_t* r, uint32_t addr) {
    asm volatile("ldmatrix.sync.aligned.m8n8.x4.trans.shared.b16 {%0,%1,%2,%3}, [%4];"
                 : "=r"(r[0]), "=r"(r[1]), "=r"(r[2]), "=r"(r[3]) : "r"(addr));
}
__device__ __forceinline__ void mma_f16(float* d, const uint32_t* a, const uint32_t* b) {
    asm volatile("mma.sync.aligned.m16n8k16.row.col.f32.f16.f16.f32 "
                 "{%0,%1,%2,%3}, {%4,%5,%6,%7}, {%8,%9}, {%0,%1,%2,%3};"
                 : "+f"(d[0]), "+f"(d[1]), "+f"(d[2]), "+f"(d[3])
                 : "r"(a[0]), "r"(a[1]), "r"(a[2]), "r"(a[3]), "r"(b[0]), "r"(b[1]));
}
__device__ __forceinline__ uint32_t packh2(float x0, float x1) {  // lo=x0, hi=x1
    uint32_t p; asm("cvt.rn.f16x2.f32 %0, %1, %2;" : "=r"(p) : "f"(x1), "f"(x0));
    return p;
}
__device__ __forceinline__ uint32_t hmul2(uint32_t a, uint32_t b) {
    uint32_t d; asm("mul.rn.f16x2 %0, %1, %2;" : "=r"(d) : "r"(a), "r"(b)); return d;
}
__device__ __forceinline__ uint32_t hadd2(uint32_t a, uint32_t b) {
    uint32_t d; asm("add.rn.f16x2 %0, %1, %2;" : "=r"(d) : "r"(a), "r"(b)); return d;
}
__device__ __forceinline__ uint32_t ex2h2(uint32_t a) {
    uint32_t d; asm("ex2.approx.f16x2 %0, %1;" : "=r"(d) : "r"(a)); return d;
}
__device__ __forceinline__ float h2sumf(uint32_t h) {
    float a, b;
    asm("{ .reg .b16 l, u; mov.b32 {l, u}, %2; cvt.f32.f16 %0, l; cvt.f32.f16 %1, u; }"
        : "=f"(a), "=f"(b) : "r"(h));
    return a + b;
}

#define CP_COMMIT asm volatile("cp.async.commit_group;" ::: "memory")
#define CP_WAIT0  asm volatile("cp.async.wait_group 0;" ::: "memory")
#define CP_WAIT1  asm volatile("cp.async.wait_group 1;" ::: "memory")
#define CP_WAIT2  asm volatile("cp.async.wait_group 2;" ::: "memory")

// copy rows x 128B tile (64 fp16 per row) gmem -> swizzled smem
template <int NT>
__device__ __forceinline__ void cpa_tile(uint32_t sdst, const __half* g,
                                         int rows, int stride, int tid) {
    int n = rows * 8;
    for (int idx = tid; idx < n; idx += NT) {
        int r = idx >> 3, c = idx & 7;
        uint32_t d = sdst + r * 128 + ((c ^ (r & 7)) << 4);
        const __half* s = g + (size_t)r * stride + c * 8;
        asm volatile("cp.async.cg.shared.global [%0], [%1], 16;" :: "r"(d), "l"(s));
    }
}

constexpr float SCL = 0.18033688011112042f;  // log2(e)/8

// ---------------------------------------------------------------------------
// Kernel 1: A = fp16(cos(x+theta)), head-major layout  (MUFU cos)
// ---------------------------------------------------------------------------
__global__ __launch_bounds__(256) void cos_kernel(const float* __restrict__ x,
                                                  const float* __restrict__ theta) {
    int t = blockIdx.x * 256 + threadIdx.x;
    int base = t * 4;
    int e = base & (Ec - 1), bs = base >> 9;
    int d = e & (DKc - 1), h = e >> 6;
    int b = bs >> 11, s = bs & (Sc - 1);

    float4 xv = *reinterpret_cast<const float4*>(x + base);
    float4 tv = *reinterpret_cast<const float4*>(theta + d);
    float c0 = __cosf(xv.x + tv.x), c1 = __cosf(xv.y + tv.y);
    float c2 = __cosf(xv.z + tv.z), c3 = __cosf(xv.w + tv.w);

    size_t o = (((size_t)(b * Hc + h) * Sc) + s) * DKc + d;
    *reinterpret_cast<uint2*>(&g_Af[o]) = make_uint2(packh2(c0, c1), packh2(c2, c3));
}

// ---------------------------------------------------------------------------
// Kernel 2: W -> fp16
// ---------------------------------------------------------------------------
__global__ __launch_bounds__(256) void w_half_kernel(const float* __restrict__ W) {
    int base = (blockIdx.x * 256 + threadIdx.x) * 4;
    float4 wv = *reinterpret_cast<const float4*>(W + base);
    *reinterpret_cast<uint2*>(&g_Wf[base]) =
        make_uint2(packh2(wv.x, wv.y), packh2(wv.z, wv.w));
}

// ---------------------------------------------------------------------------
// Kernel 3: flash attention (R7 structure), fp16 mma.sync, m32 rows/warp,
// 4 warps, whole-tile MMA1 -> softmax -> MMA2.
// NEW: K-tile visit order rotated per CTA parity (valid: bounded softmax is
// order-invariant) to anti-phase the two co-resident CTAs per SM.
// SMEM: Q 16KB | 3 x 8KB K ring = 40960 B; 2 CTAs/SM (8 warps/SM)
// ---------------------------------------------------------------------------
constexpr int SM_KB   = 16384;
constexpr int KBUF    = 8192;
constexpr int FL_SMEM = SM_KB + 3 * KBUF;

__global__ void __launch_bounds__(128, 2) flash_mma_kernel() {
    extern __shared__ char smem[];
    const uint32_t sb = smem_u32(smem);
    const int tid = threadIdx.x, lane = tid & 31, w = tid >> 5;
    const int qt = blockIdx.x, h = blockIdx.y, b = blockIdx.z;
    const __half* Af = g_Af + (size_t)(b * Hc + h) * Sc * DKc;

    // phase rotation: adjacent qt (co-scheduled on one SM) start 16 tiles apart
    const int off = (qt & 1) << 4;

    cpa_tile<128>(sb, Af + qt * 128 * 64, 128, 64, tid);
    CP_COMMIT;
    cpa_tile<128>(sb + SM_KB, Af + ((0 + off) & 31) * 64 * 64, 64, 64, tid);
    CP_COMMIT;
    cpa_tile<128>(sb + SM_KB + KBUF, Af + ((1 + off) & 31) * 64 * 64, 64, 64, tid);
    CP_COMMIT;
    CP_WAIT2;                    // Q landed
    __syncthreads();

    // Q fragments for row blocks A (32w..+15) and B (32w+16..+31)
    uint32_t qA[16], qB[16];
    {
        int rowA = 32 * w + (lane & 7) + (((lane >> 3) & 1) << 3);
        int rowB = rowA + 16;
#pragma unroll
        for (int ks = 0; ks < 4; ks++) {
            int c = 2 * ks + (lane >> 4);
            ldsm_x4(qA + ks * 4, sb + rowA * 128 + ((c ^ (rowA & 7)) << 4));
            ldsm_x4(qB + ks * 4, sb + rowB * 128 + ((c ^ (rowB & 7)) << 4));
        }
    }

    float OA[32], OB[32];
#pragma unroll
    for (int i = 0; i < 32; i++) { OA[i] = 0.f; OB[i] = 0.f; }
    float lA0 = 0.f, lA1 = 0.f, lB0 = 0.f, lB1 = 0.f;

    const int brow0 = (lane & 7) + ((lane >> 4) << 3);
    const uint32_t SCL2 = packh2(SCL, SCL);

#pragma unroll 1
    for (int kt = 0; kt < 32; kt++) {
        if (kt == 31) { CP_WAIT0; } else { CP_WAIT1; }
        __syncthreads();
        if (kt + 2 < 32) {
            cpa_tile<128>(sb + SM_KB + ((kt + 2) % 3) * KBUF,
                          Af + ((kt + 2 + off) & 31) * 64 * 64, 64, 64, tid);
            CP_COMMIT;
        }
        const uint32_t kb = sb + SM_KB + (kt % 3) * KBUF;

        // ---- MMA1: S = Q K^T for both row blocks (K frags loaded once)
        float SA[32], SB[32];
#pragma unroll
        for (int i = 0; i < 32; i++) { SA[i] = 0.f; SB[i] = 0.f; }
#pragma unroll
        for (int ks = 0; ks < 4; ks++) {
            int c = 2 * ks + ((lane >> 3) & 1);
#pragma unroll
            for (int np = 0; np < 4; np++) {
                int r = np * 16 + brow0;
                uint32_t bf[4];
                ldsm_x4(bf, kb + r * 128 + ((c ^ (r & 7)) << 4));
                mma_f16(SA + np * 8,     qA + ks * 4, bf);
                mma_f16(SA + np * 8 + 4, qA + ks * 4, bf + 2);
                mma_f16(SB + np * 8,     qB + ks * 4, bf);
                mma_f16(SB + np * 8 + 4, qB + ks * 4, bf + 2);
            }
        }

        // ---- softmax in f16x2 (bounded; exp output IS the MMA2 A-fragment)
        uint32_t cA[8], dA[8], cB[8], dB[8];
#pragma unroll
        for (int j = 0; j < 8; j++) {
            cA[j] = ex2h2(hmul2(packh2(SA[j * 4 + 0], SA[j * 4 + 1]), SCL2));
            dA[j] = ex2h2(hmul2(packh2(SA[j * 4 + 2], SA[j * 4 + 3]), SCL2));
            cB[j] = ex2h2(hmul2(packh2(SB[j * 4 + 0], SB[j * 4 + 1]), SCL2));
            dB[j] = ex2h2(hmul2(packh2(SB[j * 4 + 2], SB[j * 4 + 3]), SCL2));
        }
        lA0 += h2sumf(hadd2(hadd2(hadd2(cA[0], cA[1]), hadd2(cA[2], cA[3])),
                            hadd2(hadd2(cA[4], cA[5]), hadd2(cA[6], cA[7]))));
        lA1 += h2sumf(hadd2(hadd2(hadd2(dA[0], dA[1]), hadd2(dA[2], dA[3])),
                            hadd2(hadd2(dA[4], dA[5]), hadd2(dA[6], dA[7]))));
        lB0 += h2sumf(hadd2(hadd2(hadd2(cB[0], cB[1]), hadd2(cB[2], cB[3])),
                            hadd2(hadd2(cB[4], cB[5]), hadd2(cB[6], cB[7]))));
        lB1 += h2sumf(hadd2(hadd2(hadd2(dB[0], dB[1]), hadd2(dB[2], dB[3])),
                            hadd2(hadd2(dB[4], dB[5]), hadd2(dB[6], dB[7]))));

        // ---- MMA2: O += P V (V tile == K tile; V frags loaded once)
#pragma unroll
        for (int ks = 0; ks < 4; ks++) {
            uint32_t pfA[4] = { cA[2 * ks], dA[2 * ks], cA[2 * ks + 1], dA[2 * ks + 1] };
            uint32_t pfB[4] = { cB[2 * ks], dB[2 * ks], cB[2 * ks + 1], dB[2 * ks + 1] };
            int vrow = 16 * ks + (lane & 7) + (((lane >> 3) & 1) << 3);
#pragma unroll
            for (int nd = 0; nd < 4; nd++) {
                int c = nd * 2 + (lane >> 4);
                uint32_t vf[4];
                ldsm_x4_t(vf, kb + vrow * 128 + ((c ^ (vrow & 7)) << 4));
                mma_f16(OA + nd * 8,     pfA, vf);
                mma_f16(OA + nd * 8 + 4, pfA, vf + 2);
                mma_f16(OB + nd * 8,     pfB, vf);
                mma_f16(OB + nd * 8 + 4, pfB, vf + 2);
            }
        }
    }

    // deferred cross-lane l reductions (cols split across lane groups of 4)
#pragma unroll
    for (int off2 = 1; off2 <= 2; off2 <<= 1) {
        lA0 += __shfl_xor_sync(0xffffffffu, lA0, off2);
        lA1 += __shfl_xor_sync(0xffffffffu, lA1, off2);
        lB0 += __shfl_xor_sync(0xffffffffu, lB0, off2);
        lB1 += __shfl_xor_sync(0xffffffffu, lB1, off2);
    }

    // ---- normalize + write AO fp16 ([b][s][e], e = h*64+d)
    float iA0 = 1.f / lA0, iA1 = 1.f / lA1, iB0 = 1.f / lB0, iB1 = 1.f / lB1;
    int r0 = qt * 128 + 32 * w + (lane >> 2);
    int colb = h * 64 + 2 * (lane & 3);
#pragma unroll
    for (int j = 0; j < 8; j++) {
        int col = colb + j * 8;
        size_t i0 = (size_t)(b * Sc + r0) * Ec + col;
        *reinterpret_cast<uint32_t*>(&g_AOf[i0]) =
            packh2(OA[j * 4 + 0] * iA0, OA[j * 4 + 1] * iA0);
        *reinterpret_cast<uint32_t*>(&g_AOf[i0 + 8 * Ec]) =
            packh2(OA[j * 4 + 2] * iA1, OA[j * 4 + 3] * iA1);
        *reinterpret_cast<uint32_t*>(&g_AOf[i0 + 16 * Ec]) =
            packh2(OB[j * 4 + 0] * iB0, OB[j * 4 + 1] * iB0);
        *reinterpret_cast<uint32_t*>(&g_AOf[i0 + 24 * Ec]) =
            packh2(OB[j * 4 + 2] * iB1, OB[j * 4 + 3] * iB1);
    }
}

// ---------------------------------------------------------------------------
// Kernel 4: epilogue GEMM out = AO @ W^T + b, fp16, m32/warp (M-tile 256)
// per chunk buffer: AOf 32K | Wf 8K = 40K; double buffered = 80K; 2 CTAs/SM
// ---------------------------------------------------------------------------
constexpr int GB = 40960;
constexpr int GEMM_SMEM = 2 * GB;

__global__ void __launch_bounds__(256, 2) gemm_mma_kernel(const float* __restrict__ bias,
                                                          float* __restrict__ out) {
    extern __shared__ char smem[];
    const uint32_t sb = smem_u32(smem);
    const int tid = threadIdx.x, lane = tid & 31, w = tid >> 5;
    const int n0 = blockIdx.x * 64, m0 = blockIdx.y * 256;

    for (int c = 0; c < 2; c++) {
        uint32_t base = sb + c * GB;
        cpa_tile<256>(base,         g_AOf + (size_t)m0 * Ec + c * 64, 256, Ec, tid);
        cpa_tile<256>(base + 32768, g_Wf  + (size_t)n0 * Ec + c * 64,  64, Ec, tid);
        CP_COMMIT;
    }

    float OA[32], OB[32];
#pragma unroll
    for (int i = 0; i < 32; i++) { OA[i] = 0.f; OB[i] = 0.f; }

    const int brow0 = (lane & 7) + ((lane >> 4) << 3);

#pragma unroll 1
    for (int ch = 0; ch < 8; ch++) {
        if (ch == 7) { CP_WAIT0; } else { CP_WAIT1; }
        __syncthreads();
        uint32_t base = sb + (ch & 1) * GB;

        int arowA = 32 * w + (lane & 7) + (((lane >> 3) & 1) << 3);
        int arowB = arowA + 16;
#pragma unroll
        for (int ks = 0; ks < 4; ks++) {
            int ca = 2 * ks + (lane >> 4);
            uint32_t aA[4], aB[4];
            ldsm_x4(aA, base + arowA * 128 + ((ca ^ (arowA & 7)) << 4));
            ldsm_x4(aB, base + arowB * 128 + ((ca ^ (arowB & 7)) << 4));
            int cb = 2 * ks + ((lane >> 3) & 1);
#pragma unroll
            for (int np = 0; np < 4; np++) {
                int r = np * 16 + brow0;
                uint32_t bf[4];
                ldsm_x4(bf, base + 32768 + r * 128 + ((cb ^ (r & 7)) << 4));
                mma_f16(OA + np * 8,     aA, bf);
                mma_f16(OA + np * 8 + 4, aA, bf + 2);
                mma_f16(OB + np * 8,     aB, bf);
                mma_f16(OB + np * 8 + 4, aB, bf + 2);
            }
        }
        __syncthreads();
        if (ch + 2 < 8) {
            uint32_t nb2 = sb + (ch & 1) * GB;
            int c2 = ch + 2;
            cpa_tile<256>(nb2,         g_AOf + (size_t)m0 * Ec + c2 * 64, 256, Ec, tid);
            cpa_tile<256>(nb2 + 32768, g_Wf  + (size_t)n0 * Ec + c2 * 64,  64, Ec, tid);
            CP_COMMIT;
        }
    }

    int m = m0 + 32 * w + (lane >> 2);
    int nb = n0 + 2 * (lane & 3);
#pragma unroll
    for (int j = 0; j < 8; j++) {
        int n = nb + j * 8;
        float b0 = bias[n], b1 = bias[n + 1];
        *reinterpret_cast<float2*>(&out[(size_t)m * Ec + n]) =
            make_float2(OA[j * 4 + 0] + b0, OA[j * 4 + 1] + b1);
        *reinterpret_cast<float2*>(&out[(size_t)(m + 8) * Ec + n]) =
            make_float2(OA[j * 4 + 2] + b0, OA[j * 4 + 3] + b1);
        *reinterpret_cast<float2*>(&out[(size_t)(m + 16) * Ec + n]) =
            make_float2(OB[j * 4 + 0] + b0, OB[j * 4 + 1] + b1);
        *reinterpret_cast<float2*>(&out[(size_t)(m + 24) * Ec + n]) =
            make_float2(OB[j * 4 + 2] + b0, OB[j * 4 + 3] + b1);
    }
}

// ---------------------------------------------------------------------------
extern "C" void kernel_launch(void* const* d_in, const int* in_sizes, int n_in,
                              void* d_out, int out_size) {
    const float* x     = (const float*)d_in[0];
    const float* theta = (const float*)d_in[1];
    const float* W     = (const float*)d_in[2];
    const float* bias  = (const float*)d_in[3];
    float* out = (float*)d_out;

    cudaFuncSetAttribute(flash_mma_kernel, cudaFuncAttributeMaxDynamicSharedMemorySize, FL_SMEM);
    cudaFuncSetAttribute(gemm_mma_kernel, cudaFuncAttributeMaxDynamicSharedMemorySize, GEMM_SMEM);

    cos_kernel<<<(Bc * Sc * Ec / 4) / 256, 256>>>(x, theta);
    w_half_kernel<<<(Ec * Ec / 4) / 256, 256>>>(W);

    dim3 fgrid(Sc / 128, Hc, Bc);
    flash_mma_kernel<<<fgrid, 128, FL_SMEM>>>();

    dim3 ggrid(Ec / 64, (Bc * Sc) / 256);
    gemm_mma_kernel<<<ggrid, 256, GEMM_SMEM>>>(bias, out);
}

// round 15
// speedup vs baseline: 1.0022x; 1.0022x over previous
#include <cuda_runtime.h>
#include <cuda_fp16.h>
#include <cstdint>

constexpr int Bc = 4, Sc = 2048, Ec = 512, Hc = 8, DKc = 64;

__device__ __align__(256) __half g_Af [Bc * Hc * Sc * DKc];  // fp16 cos(x+theta), head-major
__device__ __align__(256) __half g_AOf[Bc * Sc * Ec];        // attention out, fp16
__device__ __align__(256) __half g_Wf [Ec * Ec];             // W fp16

// ---------------------------------------------------------------------------
// helpers
// ---------------------------------------------------------------------------
__device__ __forceinline__ uint32_t smem_u32(const void* p) {
    uint32_t a;
    asm("{ .reg .u64 t; cvta.to.shared.u64 t, %1; cvt.u32.u64 %0, t; }" : "=r"(a) : "l"(p));
    return a;
}
__device__ __forceinline__ void ldsm_x4(uint32_t* r, uint32_t addr) {
    asm volatile("ldmatrix.sync.aligned.m8n8.x4.shared.b16 {%0,%1,%2,%3}, [%4];"
                 : "=r"(r[0]), "=r"(r[1]), "=r"(r[2]), "=r"(r[3]) : "r"(addr));
}
__device__ __forceinline__ void ldsm_x4_t(uint32_t* r, uint32_t addr) {
    asm volatile("ldmatrix.sync.aligned.m8n8.x4.trans.shared.b16 {%0,%1,%2,%3}, [%4];"
                 : "=r"(r[0]), "=r"(r[1]), "=r"(r[2]), "=r"(r[3]) : "r"(addr));
}
__device__ __forceinline__ void mma_f16(float* d, const uint32_t* a, const uint32_t* b) {
    asm volatile("mma.sync.aligned.m16n8k16.row.col.f32.f16.f16.f32 "
                 "{%0,%1,%2,%3}, {%4,%5,%6,%7}, {%8,%9}, {%0,%1,%2,%3};"
                 : "+f"(d[0]), "+f"(d[1]), "+f"(d[2]), "+f"(d[3])
                 : "r"(a[0]), "r"(a[1]), "r"(a[2]), "r"(a[3]), "r"(b[0]), "r"(b[1]));
}
__device__ __forceinline__ uint32_t packh2(float x0, float x1) {  // lo=x0, hi=x1
    uint32_t p; asm("cvt.rn.f16x2.f32 %0, %1, %2;" : "=r"(p) : "f"(x1), "f"(x0));
    return p;
}
__device__ __forceinline__ uint32_t hmul2(uint32_t a, uint32_t b) {
    uint32_t d; asm("mul.rn.f16x2 %0, %1, %2;" : "=r"(d) : "r"(a), "r"(b)); return d;
}
__device__ __forceinline__ uint32_t hadd2(uint32_t a, uint32_t b) {
    uint32_t d; asm("add.rn.f16x2 %0, %1, %2;" : "=r"(d) : "r"(a), "r"(b)); return d;
}
__device__ __forceinline__ uint32_t ex2h2(uint32_t a) {
    uint32_t d; asm("ex2.approx.f16x2 %0, %1;" : "=r"(d) : "r"(a)); return d;
}
__device__ __forceinline__ float h2sumf(uint32_t h) {
    float a, b;
    asm("{ .reg .b16 l, u; mov.b32 {l, u}, %2; cvt.f32.f16 %0, l; cvt.f32.f16 %1, u; }"
        : "=f"(a), "=f"(b) : "r"(h));
    return a + b;
}

#define CP_COMMIT asm volatile("cp.async.commit_group;" ::: "memory")
#define CP_WAIT0  asm volatile("cp.async.wait_group 0;" ::: "memory")
#define CP_WAIT1  asm volatile("cp.async.wait_group 1;" ::: "memory")
#define CP_WAIT2  asm volatile("cp.async.wait_group 2;" ::: "memory")

// copy rows x 128B tile (64 fp16 per row) gmem -> swizzled smem
template <int NT>
__device__ __forceinline__ void cpa_tile(uint32_t sdst, const __half* g,
                                         int rows, int stride, int tid) {
    int n = rows * 8;
    for (int idx = tid; idx < n; idx += NT) {
        int r = idx >> 3, c = idx & 7;
        uint32_t d = sdst + r * 128 + ((c ^ (r & 7)) << 4);
        const __half* s = g + (size_t)r * stride + c * 8;
        asm volatile("cp.async.cg.shared.global [%0], [%1], 16;" :: "r"(d), "l"(s));
    }
}

constexpr float SCL = 0.18033688011112042f;  // log2(e)/8
constexpr int COS_BLOCKS = (Bc * Sc * Ec / 4) / 256;   // 4096
constexpr int W_BLOCKS   = (Ec * Ec / 4) / 256;        // 256

// ---------------------------------------------------------------------------
// Kernel 1 (merged): A = fp16(cos(x+theta)) head-major, and W -> fp16
// ---------------------------------------------------------------------------
__global__ __launch_bounds__(256) void prep_kernel(const float* __restrict__ x,
                                                   const float* __restrict__ theta,
                                                   const float* __restrict__ W) {
    int blk = blockIdx.x;
    if (blk < COS_BLOCKS) {
        int base = (blk * 256 + threadIdx.x) * 4;
        int e = base & (Ec - 1), bs = base >> 9;
        int d = e & (DKc - 1), h = e >> 6;
        int b = bs >> 11, s = bs & (Sc - 1);

        float4 xv = *reinterpret_cast<const float4*>(x + base);
        float4 tv = *reinterpret_cast<const float4*>(theta + d);
        float c0 = __cosf(xv.x + tv.x), c1 = __cosf(xv.y + tv.y);
        float c2 = __cosf(xv.z + tv.z), c3 = __cosf(xv.w + tv.w);

        size_t o = (((size_t)(b * Hc + h) * Sc) + s) * DKc + d;
        *reinterpret_cast<uint2*>(&g_Af[o]) = make_uint2(packh2(c0, c1), packh2(c2, c3));
    } else {
        int base = ((blk - COS_BLOCKS) * 256 + threadIdx.x) * 4;
        float4 wv = *reinterpret_cast<const float4*>(W + base);
        *reinterpret_cast<uint2*>(&g_Wf[base]) =
            make_uint2(packh2(wv.x, wv.y), packh2(wv.z, wv.w));
    }
}

// ---------------------------------------------------------------------------
// Kernel 2: flash attention, fp16 mma.sync, m32 rows/warp, 4 warps,
// whole-tile MMA1 -> softmax -> MMA2.
// 4-buffer K ring, sync only at EVEN kt (wait_group 0 + barrier), both
// next tiles prefetched there. Odd iterations are sync-free -> warps drift
// out of softmax phase with each other (de-phases MUFU bursts from HMMA).
// SMEM: Q 16KB | 4 x 8KB K ring = 49152 B; 2 CTAs/SM (8 warps/SM)
// ---------------------------------------------------------------------------
constexpr int SM_KB   = 16384;
constexpr int KBUF    = 8192;
constexpr int FL_SMEM = SM_KB + 4 * KBUF;

__global__ void __launch_bounds__(128, 2) flash_mma_kernel() {
    extern __shared__ char smem[];
    const uint32_t sb = smem_u32(smem);
    const int tid = threadIdx.x, lane = tid & 31, w = tid >> 5;
    const int qt = blockIdx.x, h = blockIdx.y, b = blockIdx.z;
    const __half* Af = g_Af + (size_t)(b * Hc + h) * Sc * DKc;

    // prologue: Q (g0), K0 (g1), K1 (g2)
    cpa_tile<128>(sb, Af + qt * 128 * 64, 128, 64, tid);
    CP_COMMIT;
    cpa_tile<128>(sb + SM_KB, Af, 64, 64, tid);
    CP_COMMIT;
    cpa_tile<128>(sb + SM_KB + KBUF, Af + 64 * 64, 64, 64, tid);
    CP_COMMIT;
    CP_WAIT2;                    // Q landed
    __syncthreads();

    // Q fragments for row blocks A (32w..+15) and B (32w+16..+31)
    uint32_t qA[16], qB[16];
    {
        int rowA = 32 * w + (lane & 7) + (((lane >> 3) & 1) << 3);
        int rowB = rowA + 16;
#pragma unroll
        for (int ks = 0; ks < 4; ks++) {
            int c = 2 * ks + (lane >> 4);
            ldsm_x4(qA + ks * 4, sb + rowA * 128 + ((c ^ (rowA & 7)) << 4));
            ldsm_x4(qB + ks * 4, sb + rowB * 128 + ((c ^ (rowB & 7)) << 4));
        }
    }

    float OA[32], OB[32];
#pragma unroll
    for (int i = 0; i < 32; i++) { OA[i] = 0.f; OB[i] = 0.f; }
    float lA0 = 0.f, lA1 = 0.f, lB0 = 0.f, lB1 = 0.f;

    const int brow0 = (lane & 7) + ((lane >> 4) << 3);
    const uint32_t SCL2 = packh2(SCL, SCL);

#pragma unroll 1
    for (int kt = 0; kt < 32; kt++) {
        if ((kt & 1) == 0) {
            // even boundary: ALL outstanding copies visible, then barrier.
            // Guarantees tiles kt, kt+1 complete (committed >=2 iters ago) and
            // all warps are past iter kt-1 before bufs (kt+2)&3,(kt+3)&3 are
            // overwritten (those were read at iters kt-2, kt-1).
            CP_WAIT0;
            __syncthreads();
            if (kt + 2 < 32) {
                cpa_tile<128>(sb + SM_KB + ((kt + 2) & 3) * KBUF,
                              Af + (kt + 2) * 64 * 64, 64, 64, tid);
                CP_COMMIT;
            }
            if (kt + 3 < 32) {
                cpa_tile<128>(sb + SM_KB + ((kt + 3) & 3) * KBUF,
                              Af + (kt + 3) * 64 * 64, 64, 64, tid);
                CP_COMMIT;
            }
        }
        const uint32_t kb = sb + SM_KB + (kt & 3) * KBUF;

        // ---- MMA1: S = Q K^T for both row blocks (K frags loaded once)
        float SA[32], SB[32];
#pragma unroll
        for (int i = 0; i < 32; i++) { SA[i] = 0.f; SB[i] = 0.f; }
#pragma unroll
        for (int ks = 0; ks < 4; ks++) {
            int c = 2 * ks + ((lane >> 3) & 1);
#pragma unroll
            for (int np = 0; np < 4; np++) {
                int r = np * 16 + brow0;
                uint32_t bf[4];
                ldsm_x4(bf, kb + r * 128 + ((c ^ (r & 7)) << 4));
                mma_f16(SA + np * 8,     qA + ks * 4, bf);
                mma_f16(SA + np * 8 + 4, qA + ks * 4, bf + 2);
                mma_f16(SB + np * 8,     qB + ks * 4, bf);
                mma_f16(SB + np * 8 + 4, qB + ks * 4, bf + 2);
            }
        }

        // ---- softmax in f16x2 (bounded; exp output IS the MMA2 A-fragment)
        uint32_t cA[8], dA[8], cB[8], dB[8];
#pragma unroll
        for (int j = 0; j < 8; j++) {
            cA[j] = ex2h2(hmul2(packh2(SA[j * 4 + 0], SA[j * 4 + 1]), SCL2));
            dA[j] = ex2h2(hmul2(packh2(SA[j * 4 + 2], SA[j * 4 + 3]), SCL2));
            cB[j] = ex2h2(hmul2(packh2(SB[j * 4 + 0], SB[j * 4 + 1]), SCL2));
            dB[j] = ex2h2(hmul2(packh2(SB[j * 4 + 2], SB[j * 4 + 3]), SCL2));
        }
        lA0 += h2sumf(hadd2(hadd2(hadd2(cA[0], cA[1]), hadd2(cA[2], cA[3])),
                            hadd2(hadd2(cA[4], cA[5]), hadd2(cA[6], cA[7]))));
        lA1 += h2sumf(hadd2(hadd2(hadd2(dA[0], dA[1]), hadd2(dA[2], dA[3])),
                            hadd2(hadd2(dA[4], dA[5]), hadd2(dA[6], dA[7]))));
        lB0 += h2sumf(hadd2(hadd2(hadd2(cB[0], cB[1]), hadd2(cB[2], cB[3])),
                            hadd2(hadd2(cB[4], cB[5]), hadd2(cB[6], cB[7]))));
        lB1 += h2sumf(hadd2(hadd2(hadd2(dB[0], dB[1]), hadd2(dB[2], dB[3])),
                            hadd2(hadd2(dB[4], dB[5]), hadd2(dB[6], dB[7]))));

        // ---- MMA2: O += P V (V tile == K tile; V frags loaded once)
#pragma unroll
        for (int ks = 0; ks < 4; ks++) {
            uint32_t pfA[4] = { cA[2 * ks], dA[2 * ks], cA[2 * ks + 1], dA[2 * ks + 1] };
            uint32_t pfB[4] = { cB[2 * ks], dB[2 * ks], cB[2 * ks + 1], dB[2 * ks + 1] };
            int vrow = 16 * ks + (lane & 7) + (((lane >> 3) & 1) << 3);
#pragma unroll
            for (int nd = 0; nd < 4; nd++) {
                int c = nd * 2 + (lane >> 4);
                uint32_t vf[4];
                ldsm_x4_t(vf, kb + vrow * 128 + ((c ^ (vrow & 7)) << 4));
                mma_f16(OA + nd * 8,     pfA, vf);
                mma_f16(OA + nd * 8 + 4, pfA, vf + 2);
                mma_f16(OB + nd * 8,     pfB, vf);
                mma_f16(OB + nd * 8 + 4, pfB, vf + 2);
            }
        }
    }

    // deferred cross-lane l reductions (cols split across lane groups of 4)
#pragma unroll
    for (int off = 1; off <= 2; off <<= 1) {
        lA0 += __shfl_xor_sync(0xffffffffu, lA0, off);
        lA1 += __shfl_xor_sync(0xffffffffu, lA1, off);
        lB0 += __shfl_xor_sync(0xffffffffu, lB0, off);
        lB1 += __shfl_xor_sync(0xffffffffu, lB1, off);
    }

    // ---- normalize + write AO fp16 ([b][s][e], e = h*64+d)
    float iA0 = 1.f / lA0, iA1 = 1.f / lA1, iB0 = 1.f / lB0, iB1 = 1.f / lB1;
    int r0 = qt * 128 + 32 * w + (lane >> 2);
    int colb = h * 64 + 2 * (lane & 3);
#pragma unroll
    for (int j = 0; j < 8; j++) {
        int col = colb + j * 8;
        size_t i0 = (size_t)(b * Sc + r0) * Ec + col;
        *reinterpret_cast<uint32_t*>(&g_AOf[i0]) =
            packh2(OA[j * 4 + 0] * iA0, OA[j * 4 + 1] * iA0);
        *reinterpret_cast<uint32_t*>(&g_AOf[i0 + 8 * Ec]) =
            packh2(OA[j * 4 + 2] * iA1, OA[j * 4 + 3] * iA1);
        *reinterpret_cast<uint32_t*>(&g_AOf[i0 + 16 * Ec]) =
            packh2(OB[j * 4 + 0] * iB0, OB[j * 4 + 1] * iB0);
        *reinterpret_cast<uint32_t*>(&g_AOf[i0 + 24 * Ec]) =
            packh2(OB[j * 4 + 2] * iB1, OB[j * 4 + 3] * iB1);
    }
}

// ---------------------------------------------------------------------------
// Kernel 3: epilogue GEMM out = AO @ W^T + b, fp16, m32/warp (M-tile 256)
// per chunk buffer: AOf 32K | Wf 8K = 40K; double buffered = 80K; 2 CTAs/SM
// ---------------------------------------------------------------------------
constexpr int GB = 40960;
constexpr int GEMM_SMEM = 2 * GB;

__global__ void __launch_bounds__(256, 2) gemm_mma_kernel(const float* __restrict__ bias,
                                                          float* __restrict__ out) {
    extern __shared__ char smem[];
    const uint32_t sb = smem_u32(smem);
    const int tid = threadIdx.x, lane = tid & 31, w = tid >> 5;
    const int n0 = blockIdx.x * 64, m0 = blockIdx.y * 256;

    for (int c = 0; c < 2; c++) {
        uint32_t base = sb + c * GB;
        cpa_tile<256>(base,         g_AOf + (size_t)m0 * Ec + c * 64, 256, Ec, tid);
        cpa_tile<256>(base + 32768, g_Wf  + (size_t)n0 * Ec + c * 64,  64, Ec, tid);
        CP_COMMIT;
    }

    float OA[32], OB[32];
#pragma unroll
    for (int i = 0; i < 32; i++) { OA[i] = 0.f; OB[i] = 0.f; }

    const int brow0 = (lane & 7) + ((lane >> 4) << 3);

#pragma unroll 1
    for (int ch = 0; ch < 8; ch++) {
        if (ch == 7) { CP_WAIT0; } else { CP_WAIT1; }
        __syncthreads();
        uint32_t base = sb + (ch & 1) * GB;

        int arowA = 32 * w + (lane & 7) + (((lane >> 3) & 1) << 3);
        int arowB = arowA + 16;
#pragma unroll
        for (int ks = 0; ks < 4; ks++) {
            int ca = 2 * ks + (lane >> 4);
            uint32_t aA[4], aB[4];
            ldsm_x4(aA, base + arowA * 128 + ((ca ^ (arowA & 7)) << 4));
            ldsm_x4(aB, base + arowB * 128 + ((ca ^ (arowB & 7)) << 4));
            int cb = 2 * ks + ((lane >> 3) & 1);
#pragma unroll
            for (int np = 0; np < 4; np++) {
                int r = np * 16 + brow0;
                uint32_t bf[4];
                ldsm_x4(bf, base + 32768 + r * 128 + ((cb ^ (r & 7)) << 4));
                mma_f16(OA + np * 8,     aA, bf);
                mma_f16(OA + np * 8 + 4, aA, bf + 2);
                mma_f16(OB + np * 8,     aB, bf);
                mma_f16(OB + np * 8 + 4, aB, bf + 2);
            }
        }
        __syncthreads();
        if (ch + 2 < 8) {
            uint32_t nb2 = sb + (ch & 1) * GB;
            int c2 = ch + 2;
            cpa_tile<256>(nb2,         g_AOf + (size_t)m0 * Ec + c2 * 64, 256, Ec, tid);
            cpa_tile<256>(nb2 + 32768, g_Wf  + (size_t)n0 * Ec + c2 * 64,  64, Ec, tid);
            CP_COMMIT;
        }
    }

    int m = m0 + 32 * w + (lane >> 2);
    int nb = n0 + 2 * (lane & 3);
#pragma unroll
    for (int j = 0; j < 8; j++) {
        int n = nb + j * 8;
        float b0 = bias[n], b1 = bias[n + 1];
        *reinterpret_cast<float2*>(&out[(size_t)m * Ec + n]) =
            make_float2(OA[j * 4 + 0] + b0, OA[j * 4 + 1] + b1);
        *reinterpret_cast<float2*>(&out[(size_t)(m + 8) * Ec + n]) =
            make_float2(OA[j * 4 + 2] + b0, OA[j * 4 + 3] + b1);
        *reinterpret_cast<float2*>(&out[(size_t)(m + 16) * Ec + n]) =
            make_float2(OB[j * 4 + 0] + b0, OB[j * 4 + 1] + b1);
        *reinterpret_cast<float2*>(&out[(size_t)(m + 24) * Ec + n]) =
            make_float2(OB[j * 4 + 2] + b0, OB[j * 4 + 3] + b1);
    }
}

// ---------------------------------------------------------------------------
extern "C" void kernel_launch(void* const* d_in, const int* in_sizes, int n_in,
                              void* d_out, int out_size) {
    const float* x     = (const float*)d_in[0];
    const float* theta = (const float*)d_in[1];
    const float* W     = (const float*)d_in[2];
    const float* bias  = (const float*)d_in[3];
    float* out = (float*)d_out;

    cudaFuncSetAttribute(flash_mma_kernel, cudaFuncAttributeMaxDynamicSharedMemorySize, FL_SMEM);
    cudaFuncSetAttribute(gemm_mma_kernel, cudaFuncAttributeMaxDynamicSharedMemorySize, GEMM_SMEM);

    prep_kernel<<<COS_BLOCKS + W_BLOCKS, 256>>>(x, theta, W);

    dim3 fgrid(Sc / 128, Hc, Bc);
    flash_mma_kernel<<<fgrid, 128, FL_SMEM>>>();

    dim3 ggrid(Ec / 64, (Bc * Sc) / 256);
    gemm_mma_kernel<<<ggrid, 256, GEMM_SMEM>>>(bias, out);
}